// round 6
// baseline (speedup 1.0000x reference)
#include <cuda_runtime.h>

#define N_WIRES 4
#define N_LAYERS 3
#define BATCH 65536
#define BN_EPS 1e-5f
#define PIX_F4 196            // 784 floats = 196 float4 per sample
#define INV196 (1.0f / 196.0f)
#define FUSE_BLOCKS (BATCH / 64)   // 1024 blocks, 64 samples each
#define BN_BLOCKS 256

// ---- device scratch (no allocations allowed; no zero-init required) ----
__device__ float g_part[FUSE_BLOCKS * 8];   // per-block BN partials: 4 sums + 4 sumsqs

__device__ __forceinline__ float2 cmul(float2 a, float2 b) {
    return make_float2(a.x * b.x - a.y * b.y, a.x * b.y + a.y * b.x);
}
__device__ __forceinline__ float2 cadd(float2 a, float2 b) {
    return make_float2(a.x + b.x, a.y + b.y);
}

template <int D>
__device__ __forceinline__ void apply_gate(float2 s[16], float2 U00, float2 U01,
                                           float2 U10, float2 U11) {
#pragma unroll
    for (int i = 0; i < 16; ++i) {
        if (i & D) continue;
        float2 a = s[i];
        float2 b = s[i | D];
        s[i]     = cadd(cmul(U00, a), cmul(U01, b));
        s[i | D] = cadd(cmul(U10, a), cmul(U11, b));
    }
}

template <int C, int T>
__device__ __forceinline__ void cnot(float2 s[16]) {
#pragma unroll
    for (int i = 0; i < 16; ++i) {
        if (!(i & C) || (i & T)) continue;
        float2 t = s[i];
        s[i] = s[i | T];
        s[i | T] = t;
    }
}

template <int D>
__device__ __forceinline__ void do_wire(float2 st[16], const float2* M,
                                        float c, float s) {
    float2 M0 = M[0], M1 = M[1], M2 = M[2], M3 = M[3];
    float2 U00 = make_float2(M0.x * c + M1.x * s, M0.y * c + M1.y * s);
    float2 U01 = make_float2(M1.x * c - M0.x * s, M1.y * c - M0.y * s);
    float2 U10 = make_float2(M2.x * c + M3.x * s, M2.y * c + M3.y * s);
    float2 U11 = make_float2(M3.x * c - M2.x * s, M3.y * c - M2.y * s);
    apply_gate<D>(st, U00, U01, U10, U11);
}

// ============ kernel 1: encode + sim + linear + BN partials (fused) ============
// grid 1024 x 256. Each warp: 8 samples. Lane `it` keeps sample `it`'s encoding
// after the butterfly (all lanes hold the full sum), then lanes 0-7 simulate.
__global__ __launch_bounds__(256) void fused_kernel(const float4* __restrict__ x4,
                                                    const float* __restrict__ params,
                                                    const float* __restrict__ W,
                                                    const float* __restrict__ b,
                                                    float4* __restrict__ out) {
    __shared__ float2 sM[N_LAYERS * N_WIRES][4];
    __shared__ float  sW[16], sb[4];
    __shared__ float  s_red[8][8];

    const int tid = threadIdx.x;
    const int wrp = tid >> 5;
    const int lane = tid & 31;

    // --- per-block gate/linear precompute (redundant, trivial) ---
    if (tid < 12) {
        float t0 = params[tid * 3 + 0];
        float t1 = params[tid * 3 + 1];
        float s0, c0, s1, c1;
        sincosf(0.5f * t0, &s0, &c0);
        sincosf(0.5f * t1, &s1, &c1);
        sM[tid][0] = make_float2(c1 * c0, -c1 * s0);
        sM[tid][1] = make_float2(s1 * s0, -s1 * c0);
        sM[tid][2] = make_float2(-s1 * s0, -s1 * c0);
        sM[tid][3] = make_float2(c1 * c0, c1 * s0);
    }
    if (tid >= 16 && tid < 32) sW[tid - 16] = W[tid - 16];
    if (tid >= 32 && tid < 36) sb[tid - 32] = b[tid - 32];
    __syncthreads();

    // --- encode: warp-per-sample streaming reduction ---
    const int wbase = (blockIdx.x * 8 + wrp) * 8;   // first sample of this warp
    float e0 = 0.f, e1 = 0.f, e2 = 0.f, e3 = 0.f;   // my sample's encoding (lane<8)

#pragma unroll 2
    for (int it = 0; it < 8; ++it) {
        const float4* __restrict__ p = x4 + (size_t)(wbase + it) * PIX_F4;
        float a0 = 0.f, a1 = 0.f, a2 = 0.f, a3 = 0.f;
        float4 f; float s;
        f = __ldcs(p + lane);       s = (f.x + f.y) + (f.z + f.w); a0 += s;
        f = __ldcs(p + 32 + lane);  s = (f.x + f.y) + (f.z + f.w); if (lane < 17) a0 += s; else a1 += s;
        f = __ldcs(p + 64 + lane);  s = (f.x + f.y) + (f.z + f.w); a1 += s;
        f = __ldcs(p + 96 + lane);  s = (f.x + f.y) + (f.z + f.w); if (lane < 2)  a1 += s; else a2 += s;
        f = __ldcs(p + 128 + lane); s = (f.x + f.y) + (f.z + f.w); if (lane < 19) a2 += s; else a3 += s;
        f = __ldcs(p + 160 + lane); s = (f.x + f.y) + (f.z + f.w); a3 += s;
        if (lane < 4) {
            f = __ldcs(p + 192 + lane); s = (f.x + f.y) + (f.z + f.w); a3 += s;
        }
#pragma unroll
        for (int o = 16; o; o >>= 1) {
            a0 += __shfl_xor_sync(0xffffffffu, a0, o);
            a1 += __shfl_xor_sync(0xffffffffu, a1, o);
            a2 += __shfl_xor_sync(0xffffffffu, a2, o);
            a3 += __shfl_xor_sync(0xffffffffu, a3, o);
        }
        if (lane == it) {
            e0 = a0 * INV196; e1 = a1 * INV196; e2 = a2 * INV196; e3 = a3 * INV196;
        }
    }

    // --- sim: lanes 0-7 each own one sample (others compute dummy zeros) ---
    float cw[4], sw[4];
    sincosf(0.5f * e0, &sw[0], &cw[0]);
    sincosf(0.5f * e1, &sw[1], &cw[1]);
    sincosf(0.5f * e2, &sw[2], &cw[2]);
    sincosf(0.5f * e3, &sw[3], &cw[3]);

    float2 st[16];
#pragma unroll
    for (int i = 0; i < 16; ++i) st[i] = make_float2(0.f, 0.f);
    st[0] = make_float2(1.f, 0.f);

#pragma unroll
    for (int l = 0; l < N_LAYERS; ++l) {
        do_wire<1>(st, sM[l * 4 + 0], cw[0], sw[0]);
        cnot<1, 2>(st);
        do_wire<2>(st, sM[l * 4 + 1], cw[1], sw[1]);
        cnot<2, 4>(st);
        do_wire<4>(st, sM[l * 4 + 2], cw[2], sw[2]);
        cnot<4, 8>(st);
        do_wire<8>(st, sM[l * 4 + 3], cw[3], sw[3]);
    }

    float z[4] = {0.f, 0.f, 0.f, 0.f};
#pragma unroll
    for (int i = 0; i < 16; ++i) {
        float p = st[i].x * st[i].x + st[i].y * st[i].y;
        z[0] += (i & 1) ? -p : p;
        z[1] += (i & 2) ? -p : p;
        z[2] += (i & 4) ? -p : p;
        z[3] += (i & 8) ? -p : p;
    }

    float o[4];
#pragma unroll
    for (int j = 0; j < 4; ++j) {
        float acc = sb[j];
#pragma unroll
        for (int w = 0; w < 4; ++w) acc += z[w] * sW[j * 4 + w];
        o[j] = acc;
    }

    if (lane < 8) out[wbase + lane] = make_float4(o[0], o[1], o[2], o[3]);
    else { o[0] = 0.f; o[1] = 0.f; o[2] = 0.f; o[3] = 0.f; }

    // --- BN partials: deterministic per-block sums (no atomics, no init) ---
    float red[8] = {o[0], o[1], o[2], o[3],
                    o[0] * o[0], o[1] * o[1], o[2] * o[2], o[3] * o[3]};
#pragma unroll
    for (int k = 0; k < 8; ++k) {
        float v = red[k];
#pragma unroll
        for (int off = 16; off; off >>= 1) v += __shfl_xor_sync(0xffffffffu, v, off);
        red[k] = v;
    }
    if (lane == 0) {
#pragma unroll
        for (int k = 0; k < 8; ++k) s_red[wrp][k] = red[k];
    }
    __syncthreads();
    if (tid < 8) {
        float v = 0.f;
#pragma unroll
        for (int w = 0; w < 8; ++w) v += s_red[w][tid];
        g_part[blockIdx.x * 8 + tid] = v;
    }
}

// ============ kernel 2: reduce partials + in-place batchnorm ============
// grid 256 x 256; every block redundantly reduces the 1024x8 partials (L2-hot).
__global__ __launch_bounds__(256) void bn_kernel(float4* __restrict__ out,
                                                 const float* __restrict__ bn_w,
                                                 const float* __restrict__ bn_b) {
    __shared__ float s_tot[8];
    __shared__ float s_scale[4], s_shift[4];
    const int tid = threadIdx.x;
    const int wrp = tid >> 5;     // warp w handles channel w (0-3 sum, 4-7 sumsq)
    const int lane = tid & 31;

    float acc = 0.f;
#pragma unroll
    for (int k = 0; k < FUSE_BLOCKS / 32; ++k)
        acc += g_part[(lane + 32 * k) * 8 + wrp];
#pragma unroll
    for (int off = 16; off; off >>= 1) acc += __shfl_xor_sync(0xffffffffu, acc, off);
    if (lane == 0) s_tot[wrp] = acc;
    __syncthreads();

    if (tid < 4) {
        float mu  = s_tot[tid] * (1.0f / BATCH);
        float ex2 = s_tot[tid + 4] * (1.0f / BATCH);
        float var = ex2 - mu * mu;
        float sc = bn_w[tid] * rsqrtf(var + BN_EPS);
        s_scale[tid] = sc;
        s_shift[tid] = bn_b[tid] - mu * sc;
    }
    __syncthreads();

    const float sc0 = s_scale[0], sc1 = s_scale[1], sc2 = s_scale[2], sc3 = s_scale[3];
    const float sh0 = s_shift[0], sh1 = s_shift[1], sh2 = s_shift[2], sh3 = s_shift[3];

    int i = blockIdx.x * 256 + tid;
    float4 v = out[i];
    v.x = v.x * sc0 + sh0;
    v.y = v.y * sc1 + sh1;
    v.z = v.z * sc2 + sh2;
    v.w = v.w * sc3 + sh3;
    out[i] = v;
}

extern "C" void kernel_launch(void* const* d_in, const int* in_sizes, int n_in,
                              void* d_out, int out_size) {
    const float* x      = (const float*)d_in[0];
    const float* params = (const float*)d_in[1];
    const float* W      = (const float*)d_in[2];
    const float* b      = (const float*)d_in[3];
    const float* bn_w   = (const float*)d_in[4];
    const float* bn_b   = (const float*)d_in[5];
    float4* out = (float4*)d_out;

    fused_kernel<<<FUSE_BLOCKS, 256>>>((const float4*)x, params, W, b, out);
    bn_kernel<<<BN_BLOCKS, 256>>>(out, bn_w, bn_b);
}